// round 4
// baseline (speedup 1.0000x reference)
#include <cuda_runtime.h>
#include <cstdint>

// DepenL: out1[m] = Uk[m]*Uq[mc], out2[m] = Uk[mc]*Uq[m], mc = 9*(m/9)+4.
// m = p*L + l, U[m] = x[l/128 + p/3 - 1, l%128 + p%3 - 1] (0 outside).
// L mod 9 == 4 => mc = m + d, d = 4 - (m mod 9) in [-4,4]; center is the
// same-p unfold at pixel l+d except near plane boundaries (EDGE blocks only).

#define WW  128
#define LL  16384
#define MM  147456
#define HC  16
#define NR  20          // HC + 2*2 halo
#define RS  136         // 128 + 8 pad  -> f(l) = l + 8*(l>>7)
#define NT  256
#define SMN (NR * RS)   // 2720 floats (x4B, 16B-aligned since 2720%4==0)

template<bool EDGE>
__global__ __launch_bounds__(NT, 6)
void depenl_k(const float* __restrict__ key, const float* __restrict__ query,
              float* __restrict__ out1, float* __restrict__ out2) {
    __shared__ float sm[2 * SMN];
    float* sK = sm;
    float* sQ = sm + SMN;

    const int tid   = threadIdx.x;
    const int ch    = blockIdx.y;
    const int chunk = EDGE ? (blockIdx.x * 7) : (blockIdx.x + 1);
    const int h0    = chunk * HC;
    const int l0    = h0 * WW;

    const float* __restrict__ kb = key   + (size_t)ch * LL;
    const float* __restrict__ qb = query + (size_t)ch * LL;

    if (EDGE) {
        // zero everything (covers pad cols + out-of-image halo rows)
        for (int t = tid; t < 2 * SMN / 4; t += NT)
            reinterpret_cast<float4*>(sm)[t] = make_float4(0.f, 0.f, 0.f, 0.f);
        __syncthreads();
        for (int t = tid; t < NR * 32; t += NT) {
            const int r = t >> 5, c4 = (t & 31) * 4;
            const int gh = h0 - 2 + r;
            if ((unsigned)gh < 128u) {
                *reinterpret_cast<float4*>(&sK[r * RS + 4 + c4]) =
                    *reinterpret_cast<const float4*>(kb + gh * WW + c4);
                *reinterpret_cast<float4*>(&sQ[r * RS + 4 + c4]) =
                    *reinterpret_cast<const float4*>(qb + gh * WW + c4);
            }
        }
    } else {
        // interior: all rows in-image; zero only the 8 pad columns per row
        if (tid < NR * 8) {
            const int r = tid >> 3, c = tid & 7;
            const int col = (c < 4) ? c : (128 + c);
            sK[r * RS + col] = 0.f;
            sQ[r * RS + col] = 0.f;
        }
        for (int t = tid; t < NR * 32; t += NT) {
            const int r = t >> 5, c4 = (t & 31) * 4;
            const int gh = h0 - 2 + r;
            *reinterpret_cast<float4*>(&sK[r * RS + 4 + c4]) =
                *reinterpret_cast<const float4*>(kb + gh * WW + c4);
            *reinterpret_cast<float4*>(&sQ[r * RS + 4 + c4]) =
                *reinterpret_cast<const float4*>(qb + gh * WW + c4);
        }
    }
    __syncthreads();

    float* const o1c = out1 + (size_t)ch * MM + l0 + tid;
    float* const o2c = out2 + (size_t)ch * MM + l0 + tid;

    const int fbase = tid + ((tid >> 7) << 3);  // f(tid)
    int rp = (l0 + tid) % 9;                    // m mod 9 at p=0, it=0

    for (int p = 0; p < 9; ++p) {
        const int i  = (p * 11) >> 5;           // p/3
        const int j  = p - i * 3;               // p%3
        const int pc = (i + 1) * RS + j + 3;    // plane offset into tile
        const float* __restrict__ nK = sK + pc + fbase;
        const float* __restrict__ nQ = sQ + pc + fbase;
        const float* __restrict__ cK = sK + pc;
        const float* __restrict__ cQ = sQ + pc;
        float* __restrict__ o1 = o1c + p * LL;
        float* __restrict__ o2 = o2c + p * LL;

        int dd = 4 - rp;                        // d = 4 - (m mod 9)
        #pragma unroll
        for (int it = 0; it < (HC * WW) / NT; ++it) {
            const float kn = nK[it * 272];      // f advances by 272 per 256 elems
            const float qn = nQ[it * 272];
            const int lc   = tid + it * 256 + dd;       // center pixel (local)
            const int cidx = lc + ((lc >> 7) << 3);     // f(lc), neg-safe
            float kc = cK[cidx];
            float qc = cQ[cidx];
            if (EDGE) {
                const int glc = l0 + lc;
                if ((unsigned)glc >= (unsigned)LL) {    // center in other plane
                    const int mc  = p * LL + glc;       // global unfold index
                    const int pc2 = mc >> 14;
                    const int lc2 = mc & 16383;
                    const int ic  = (pc2 * 11) >> 5;
                    const int jc  = pc2 - ic * 3;
                    const int hc2 = (lc2 >> 7) + ic - 1;
                    const int wc2 = (lc2 & 127) + jc - 1;
                    const bool ok = ((unsigned)hc2 < 128u) && ((unsigned)wc2 < 128u);
                    const int gi  = (hc2 << 7) + wc2;
                    kc = ok ? __ldg(kb + gi) : 0.f;
                    qc = ok ? __ldg(qb + gi) : 0.f;
                }
            }
            o1[it * 256] = kn * qc;
            o2[it * 256] = kc * qn;
            dd = (dd >= 0) ? dd - 4 : dd + 5;   // m += 256 -> (m mod 9) += 4
        }
        rp += 4; if (rp >= 9) rp -= 9;          // next plane: m += L (L%9==4)
    }
}

extern "C" void kernel_launch(void* const* d_in, const int* in_sizes, int n_in,
                              void* d_out, int out_size) {
    const float* key   = (const float*)d_in[0];
    const float* query = (const float*)d_in[1];
    float* out1 = (float*)d_out;
    float* out2 = out1 + (size_t)256 * MM;

    dim3 gi(6, 256), ge(2, 256);
    depenl_k<false><<<gi, NT>>>(key, query, out1, out2);
    depenl_k<true ><<<ge, NT>>>(key, query, out1, out2);
}

// round 5
// speedup vs baseline: 1.1042x; 1.1042x over previous
#include <cuda_runtime.h>
#include <cstdint>

// DepenL: out1[m] = Uk[m]*Uq[mc], out2[m] = Uk[mc]*Uq[m], mc = 9*(m/9)+4.
// m = p*L + l, U[m] = x[l/128 + p/3 - 1, l%128 + p%3 - 1] (0 outside).
// L mod 9 == 4 => mc = m + d, d = 4 - (m mod 9) in [-4,4]; center is the
// same-p unfold at pixel l+d except near plane boundaries (edge chunks 0,7).

#define WW  128
#define LL  16384
#define MM  147456
#define HC  16
#define NR  20          // HC + 2*2 halo
#define RS  136         // 128 + 8 pad  -> f(l) = l + 8*(l>>7)
#define NT  256
#define SMN (NR * RS)   // 2720 floats

__global__ __launch_bounds__(NT)
void depenl_k(const float* __restrict__ key, const float* __restrict__ query,
              float* __restrict__ out1, float* __restrict__ out2) {
    __shared__ float sm[2 * SMN];
    float* sK = sm;
    float* sQ = sm + SMN;

    const int tid   = threadIdx.x;
    const int ch    = blockIdx.y;
    const int chunk = blockIdx.x;         // 0..7
    const int h0    = chunk * HC;
    const int l0    = h0 * WW;
    const bool edge = (chunk == 0) | (chunk == 7);

    const float* __restrict__ kb = key   + (size_t)ch * LL;
    const float* __restrict__ qb = query + (size_t)ch * LL;

    // zero pad columns (8 per row); edge blocks also zero the out-of-image
    // halo rows via the guarded fill below, so pre-zero whole halo rows there.
    if (edge) {
        for (int t = tid; t < 2 * SMN / 4; t += NT)
            reinterpret_cast<float4*>(sm)[t] = make_float4(0.f, 0.f, 0.f, 0.f);
        __syncthreads();
        for (int t = tid; t < NR * 32; t += NT) {
            const int r = t >> 5, c4 = (t & 31) * 4;
            const int gh = h0 - 2 + r;
            if ((unsigned)gh < 128u) {
                *reinterpret_cast<float4*>(&sK[r * RS + 4 + c4]) =
                    *reinterpret_cast<const float4*>(kb + gh * WW + c4);
                *reinterpret_cast<float4*>(&sQ[r * RS + 4 + c4]) =
                    *reinterpret_cast<const float4*>(qb + gh * WW + c4);
            }
        }
    } else {
        if (tid < NR * 8) {
            const int r = tid >> 3, c = tid & 7;
            const int col = (c < 4) ? c : (128 + c);
            sK[r * RS + col] = 0.f;
            sQ[r * RS + col] = 0.f;
        }
        for (int t = tid; t < NR * 32; t += NT) {
            const int r = t >> 5, c4 = (t & 31) * 4;
            const int gh = h0 - 2 + r;
            *reinterpret_cast<float4*>(&sK[r * RS + 4 + c4]) =
                *reinterpret_cast<const float4*>(kb + gh * WW + c4);
            *reinterpret_cast<float4*>(&sQ[r * RS + 4 + c4]) =
                *reinterpret_cast<const float4*>(qb + gh * WW + c4);
        }
    }
    __syncthreads();

    float* const o1c = out1 + (size_t)ch * MM + l0 + tid;
    float* const o2c = out2 + (size_t)ch * MM + l0 + tid;

    const int fbase = tid + ((tid >> 7) << 3);  // f(tid)
    int rp = (l0 + tid) % 9;                    // m mod 9 at p=0, it=0

    if (!edge) {
        // ---- interior: branch-free inner loop ----
        #pragma unroll
        for (int p = 0; p < 9; ++p) {
            const int i  = (p * 11) >> 5;
            const int j  = p - i * 3;
            const int pc = (i + 1) * RS + j + 3;
            const float* __restrict__ nK = sK + pc + fbase;
            const float* __restrict__ nQ = sQ + pc + fbase;
            const float* __restrict__ cK = sK + pc;
            const float* __restrict__ cQ = sQ + pc;
            float* __restrict__ o1 = o1c + p * LL;
            float* __restrict__ o2 = o2c + p * LL;

            int dd = 4 - rp;
            #pragma unroll
            for (int it = 0; it < (HC * WW) / NT; ++it) {
                const float kn = nK[it * 272];
                const float qn = nQ[it * 272];
                const int lc   = tid + it * 256 + dd;
                const int cidx = lc + ((lc >> 7) << 3);   // f(lc)
                const float kc = cK[cidx];
                const float qc = cQ[cidx];
                o1[it * 256] = kn * qc;
                o2[it * 256] = kc * qn;
                dd = (dd >= 0) ? dd - 4 : dd + 5;
            }
            rp += 4; if (rp >= 9) rp -= 9;
        }
    } else {
        // ---- edge chunks (0,7): same loop + cross-plane center fallback ----
        for (int p = 0; p < 9; ++p) {
            const int i  = (p * 11) >> 5;
            const int j  = p - i * 3;
            const int pc = (i + 1) * RS + j + 3;
            const float* __restrict__ nK = sK + pc + fbase;
            const float* __restrict__ nQ = sQ + pc + fbase;
            const float* __restrict__ cK = sK + pc;
            const float* __restrict__ cQ = sQ + pc;
            float* __restrict__ o1 = o1c + p * LL;
            float* __restrict__ o2 = o2c + p * LL;

            int dd = 4 - rp;
            #pragma unroll
            for (int it = 0; it < (HC * WW) / NT; ++it) {
                const float kn = nK[it * 272];
                const float qn = nQ[it * 272];
                const int lc   = tid + it * 256 + dd;
                const int cidx = lc + ((lc >> 7) << 3);
                float kc = cK[cidx];
                float qc = cQ[cidx];
                const int glc = l0 + lc;
                if ((unsigned)glc >= (unsigned)LL) {      // center in other plane
                    const int mc  = p * LL + glc;
                    const int pc2 = mc >> 14;
                    const int lc2 = mc & 16383;
                    const int ic  = (pc2 * 11) >> 5;
                    const int jc  = pc2 - ic * 3;
                    const int hc2 = (lc2 >> 7) + ic - 1;
                    const int wc2 = (lc2 & 127) + jc - 1;
                    const bool ok = ((unsigned)hc2 < 128u) && ((unsigned)wc2 < 128u);
                    const int gi  = (hc2 << 7) + wc2;
                    kc = ok ? __ldg(kb + gi) : 0.f;
                    qc = ok ? __ldg(qb + gi) : 0.f;
                }
                o1[it * 256] = kn * qc;
                o2[it * 256] = kc * qn;
                dd = (dd >= 0) ? dd - 4 : dd + 5;
            }
            rp += 4; if (rp >= 9) rp -= 9;
        }
    }
}

extern "C" void kernel_launch(void* const* d_in, const int* in_sizes, int n_in,
                              void* d_out, int out_size) {
    const float* key   = (const float*)d_in[0];
    const float* query = (const float*)d_in[1];
    float* out1 = (float*)d_out;
    float* out2 = out1 + (size_t)256 * MM;

    dim3 grid(8, 256);
    depenl_k<<<grid, NT>>>(key, query, out1, out2);
}

// round 6
// speedup vs baseline: 1.1465x; 1.0383x over previous
#include <cuda_runtime.h>
#include <cstdint>

// DepenL: out1[m] = Uk[m]*Uq[mc], out2[m] = Uk[mc]*Uq[m], mc = 9*(m/9)+4.
// m = p*L + l, U[m] = x[l/128 + p/3 - 1, l%128 + p%3 - 1] (0 outside).
// L mod 9 == 4 => mc = m + d, d = 4 - (m mod 9) in [-4,4]; center is the
// same-p unfold at pixel l+d except near plane edges (chunks 0,7 only).

#define WW  128
#define LL  16384
#define MM  147456
#define HC  16
#define NR  20          // HC + 2*2 halo
#define RS  136         // 128 + 8 pad  -> f(l) = l + 8*(l>>7)
#define NT  256
#define SMN (NR * RS)   // 2720 floats

__global__ __launch_bounds__(NT, 8)
void depenl_k(const float* __restrict__ key, const float* __restrict__ query,
              float* __restrict__ out1, float* __restrict__ out2) {
    __shared__ float sm[2 * SMN];
    float* sK = sm;
    float* sQ = sm + SMN;

    const int tid   = threadIdx.x;
    const int ch    = blockIdx.y;
    const int chunk = blockIdx.x;         // 0..7
    const int h0    = chunk * HC;
    const int l0    = h0 * WW;

    const float* __restrict__ kb = key   + (size_t)ch * LL;
    const float* __restrict__ qb = query + (size_t)ch * LL;

    // zero pad columns + (possibly out-of-image) halo rows, then fill.
    for (int t = tid; t < 2 * SMN / 4; t += NT)
        reinterpret_cast<float4*>(sm)[t] = make_float4(0.f, 0.f, 0.f, 0.f);
    __syncthreads();
    for (int t = tid; t < NR * 32; t += NT) {
        const int r = t >> 5, c4 = (t & 31) * 4;
        const int gh = h0 - 2 + r;
        if ((unsigned)gh < 128u) {
            *reinterpret_cast<float4*>(&sK[r * RS + 4 + c4]) =
                *reinterpret_cast<const float4*>(kb + gh * WW + c4);
            *reinterpret_cast<float4*>(&sQ[r * RS + 4 + c4]) =
                *reinterpret_cast<const float4*>(qb + gh * WW + c4);
        }
    }
    __syncthreads();

    float* const o1c = out1 + (size_t)ch * MM + l0 + tid;
    float* const o2c = out2 + (size_t)ch * MM + l0 + tid;

    const int fbase = tid + ((tid >> 7) << 3);  // f(tid)
    int rp = (l0 + tid) % 9;                    // m mod 9 at p=0, it=0

    #pragma unroll 1
    for (int p = 0; p < 9; ++p) {
        const int i  = (p * 11) >> 5;           // p/3
        const int j  = p - i * 3;               // p%3
        const int pc = (i + 1) * RS + j + 3;    // plane offset into tile
        const float* __restrict__ nK = sK + pc + fbase;
        const float* __restrict__ nQ = sQ + pc + fbase;
        const float* __restrict__ cK = sK + pc;
        const float* __restrict__ cQ = sQ + pc;
        float* __restrict__ o1 = o1c + p * LL;
        float* __restrict__ o2 = o2c + p * LL;

        int dd = 4 - rp;                        // d = 4 - (m mod 9)
        #pragma unroll
        for (int it = 0; it < (HC * WW) / NT; ++it) {
            const float kn = nK[it * 272];      // f advances 272 per 256 elems
            const float qn = nQ[it * 272];
            const int lc   = tid + it * 256 + dd;     // center pixel (local)
            const int cidx = lc + ((lc >> 7) << 3);   // f(lc), neg-safe
            float kc = cK[cidx];
            float qc = cQ[cidx];
            if ((unsigned)(l0 + lc) >= (unsigned)LL) {  // rare: other plane
                const int mc  = p * LL + l0 + lc;       // global unfold index
                const int pc2 = mc >> 14;
                const int lc2 = mc & 16383;
                const int ic  = (pc2 * 11) >> 5;
                const int jc  = pc2 - ic * 3;
                const int hc2 = (lc2 >> 7) + ic - 1;
                const int wc2 = (lc2 & 127) + jc - 1;
                const bool ok = ((unsigned)hc2 < 128u) && ((unsigned)wc2 < 128u);
                const int gi  = (hc2 << 7) + wc2;
                kc = ok ? __ldg(kb + gi) : 0.f;
                qc = ok ? __ldg(qb + gi) : 0.f;
            }
            o1[it * 256] = kn * qc;
            o2[it * 256] = kc * qn;
            dd = (dd >= 0) ? dd - 4 : dd + 5;   // m += 256 -> (m mod 9) += 4
        }
        rp += 4; if (rp >= 9) rp -= 9;          // next plane: m += L (L%9==4)
    }
}

extern "C" void kernel_launch(void* const* d_in, const int* in_sizes, int n_in,
                              void* d_out, int out_size) {
    const float* key   = (const float*)d_in[0];
    const float* query = (const float*)d_in[1];
    float* out1 = (float*)d_out;
    float* out2 = out1 + (size_t)256 * MM;

    dim3 grid(8, 256);
    depenl_k<<<grid, NT>>>(key, query, out1, out2);
}

// round 7
// speedup vs baseline: 1.5123x; 1.3191x over previous
#include <cuda_runtime.h>
#include <cstdint>

// DepenL via tiled shared-memory formulation (R3 structure + streaming stores).
//
// Within one channel (9L floats of unfold, L=16384), for m = p*L + l:
//   U[m] = x[h+i-1, w+j-1], h=l/128, w=l%128, i=p/3, j=p%3 (0 outside).
//   out1[m] = Uk[m] * Uq[mc], out2[m] = Uk[mc] * Uq[m], mc = 9*(m/9)+4.
// Since L mod 9 == 4:  mc = m + d,  d = 4 - ((4p + l) mod 9) in [-4,4].
// If l+d in [0,L): center = U[p, l+d] (same p, nearby pixel) -> shared memory.
// Else (<=8 elems per p-segment): full decode + global fallback.

#define WW   128
#define LL   16384
#define MM   147456   // 9*L
#define HC   16       // rows per block chunk
#define NR   (HC + 4) // stored rows (halo 2 each side)
#define RS   136      // smem row stride (floats); data at col w+4
#define NT   256

__global__ __launch_bounds__(NT)
void depenl_tile(const float* __restrict__ key,
                 const float* __restrict__ query,
                 float* __restrict__ out1,
                 float* __restrict__ out2) {
    __shared__ float sK[NR * RS];
    __shared__ float sQ[NR * RS];

    const int bx    = blockIdx.x;
    const int ch    = bx >> 3;      // 0..255  (B*C)
    const int chunk = bx & 7;       // 0..7
    const int h0    = chunk * HC;
    const int tid   = threadIdx.x;

    const float* __restrict__ kb = key   + (size_t)ch * LL;
    const float* __restrict__ qb = query + (size_t)ch * LL;

    // zero entire smem (covers pad cols, out-of-image halo rows)
    for (int idx = tid; idx < NR * RS; idx += NT) { sK[idx] = 0.f; sQ[idx] = 0.f; }
    __syncthreads();

    // fill valid rows: gh = h0-2+r, cols [4, 132) <- x[gh, 0..127]
    for (int t = tid; t < NR * 32; t += NT) {
        const int r  = t >> 5;
        const int c4 = (t & 31) * 4;
        const int gh = h0 - 2 + r;
        if ((unsigned)gh < 128u) {
            *reinterpret_cast<float4*>(&sK[r * RS + 4 + c4]) =
                *reinterpret_cast<const float4*>(kb + gh * WW + c4);
            *reinterpret_cast<float4*>(&sQ[r * RS + 4 + c4]) =
                *reinterpret_cast<const float4*>(qb + gh * WW + c4);
        }
    }
    __syncthreads();

    const int l0 = h0 * WW;
    float* __restrict__ o1c = out1 + (size_t)ch * MM;
    float* __restrict__ o2c = out2 + (size_t)ch * MM;

    for (int p = 0; p < 9; ++p) {
        const int i = (p * 11) >> 5;     // p/3
        const int j = p - i * 3;         // p%3
        int r = (4 * p + l0 + tid) % 9;  // (4p+l) mod 9, updated incrementally
        int l_loc = tid;                 // l - l0
        float* o1 = o1c + p * LL + l0 + tid;
        float* o2 = o2c + p * LL + l0 + tid;

        #pragma unroll
        for (int it = 0; it < (HC * WW) / NT; ++it) {
            const int h_loc = l_loc >> 7;          // 0..15
            const int w     = l_loc & 127;
            const int nofs  = (h_loc + i + 1) * RS + (w + j + 3);
            const float kn = sK[nofs];
            const float qn = sQ[nofs];

            const int d      = 4 - r;
            const int lc_loc = l_loc + d;          // may be -4..HC*128+3
            const int glc    = l0 + lc_loc;
            float kc, qc;
            if ((unsigned)glc < (unsigned)LL) {
                // same-p center; arithmetic >>/& handle lc_loc<0 correctly
                const int cofs = ((lc_loc >> 7) + i + 1) * RS
                               + ((lc_loc & 127) + j + 3);
                kc = sK[cofs];
                qc = sQ[cofs];
            } else {
                // rare: center falls in adjacent p-plane
                const int m   = p * LL + glc - d;  // p*LL + l
                const int mc  = m + d;
                const int pc  = mc >> 14;
                const int lc2 = mc & 16383;
                const int ic  = (pc * 11) >> 5;
                const int jc  = pc - ic * 3;
                const int hc2 = (lc2 >> 7) + ic - 1;
                const int wc2 = (lc2 & 127) + jc - 1;
                const bool ok = ((unsigned)hc2 < 128u) && ((unsigned)wc2 < 128u);
                const int gi  = (hc2 << 7) + wc2;
                kc = ok ? __ldg(kb + gi) : 0.f;
                qc = ok ? __ldg(qb + gi) : 0.f;
            }

            __stcs(o1, kn * qc);   // streaming (evict-first) store
            __stcs(o2, kc * qn);

            o1 += NT; o2 += NT;
            l_loc += NT;
            r += 4; if (r >= 9) r -= 9;
        }
    }
}

extern "C" void kernel_launch(void* const* d_in, const int* in_sizes, int n_in,
                              void* d_out, int out_size) {
    const float* key   = (const float*)d_in[0];
    const float* query = (const float*)d_in[1];
    float* out1 = (float*)d_out;
    float* out2 = out1 + (size_t)256 * MM;

    depenl_tile<<<256 * 8, NT>>>(key, query, out1, out2);
}